// round 9
// baseline (speedup 1.0000x reference)
#include <cuda_runtime.h>
#include <cuda_fp16.h>
#include <stdint.h>

// Problem constants
#define Bc 32
#define Nc 512
#define Gc 64
#define Tc 16
#define Dc 256
#define NTGT (Bc * Gc)          // 2048 goal rows
#define NSRC (Bc * Nc)          // 16384 scope rows
#define EMAX 500000
#define NB 128                  // bucketing blocks

static __device__ __constant__ float NEGV = -1.0e10f;

// Scratch (static __device__ per harness rules)
__device__ float  g_V[NTGT * Dc];      // V[g][d] = W @ goal_type[g]   (2 MB)
__device__ __half g_Sh[NSRC * Dc];     // fp16 copy of scope_type rows (8 MB)
__device__ int    g_cnt[NTGT];
__device__ int    g_base[NTGT];
__device__ int    g_mat[NTGT * NB];    // transposed [tgt][block] counts->prefixes
__device__ int2   g_pair[EMAX];        // (edge id, src) grouped by tgt (4 MB)
__device__ int    g_mask_kind;         // 0=u8, 1=i32, 2=f32

// ---------------------------------------------------------------------------
// Fused prep kernel: blocks [0,128) convert scope_type rows to fp16;
// blocks [128,192) compute V = W @ goal_type; block 192 sniffs mask dtype.
// ---------------------------------------------------------------------------
__global__ void prep_kernel(const float* __restrict__ scope,
                            const float* __restrict__ goal,
                            const float* __restrict__ W,
                            const uint32_t* __restrict__ mw) {
    const int blk = blockIdx.x;
    if (blk < 128) {
        // fp16 conversion: 128 rows per block, warp per row, 16 rows per warp
        const int w = threadIdx.x >> 5, lane = threadIdx.x & 31;
#pragma unroll 4
        for (int r = 0; r < 16; r++) {
            const int row = blk * 128 + w * 16 + r;
            const float4* src =
                reinterpret_cast<const float4*>(scope + (size_t)row * (Tc * Dc));
            float4 x = src[lane * 2], y = src[lane * 2 + 1];
            __half2 h0 = __floats2half2_rn(x.x, x.y);
            __half2 h1 = __floats2half2_rn(x.z, x.w);
            __half2 h2 = __floats2half2_rn(y.x, y.y);
            __half2 h3 = __floats2half2_rn(y.z, y.w);
            uint4 packed;
            packed.x = *reinterpret_cast<uint32_t*>(&h0);
            packed.y = *reinterpret_cast<uint32_t*>(&h1);
            packed.z = *reinterpret_cast<uint32_t*>(&h2);
            packed.w = *reinterpret_cast<uint32_t*>(&h3);
            reinterpret_cast<uint4*>(g_Sh + (size_t)row * Dc)[lane] = packed;
        }
    } else if (blk < 192) {
        // V[g][d] = sum_f W[d][f] * goal_type[g][f], 32 g's per block
        __shared__ float sg[32][Dc];           // 32 KB
        const int g0 = (blk - 128) * 32;
        for (int i = threadIdx.x; i < 32 * Dc; i += blockDim.x) {
            int g = i >> 8, f = i & 255;
            sg[g][f] = goal[(size_t)(g0 + g) * (Tc * Dc) + f];
        }
        __syncthreads();
        const int d = threadIdx.x;
        float acc[32];
#pragma unroll
        for (int g = 0; g < 32; g++) acc[g] = 0.f;
        const float4* Wrow = reinterpret_cast<const float4*>(W + (size_t)d * Dc);
#pragma unroll 4
        for (int f4 = 0; f4 < Dc / 4; f4++) {
            float4 w = Wrow[f4];
#pragma unroll
            for (int g = 0; g < 32; g++) {
                float4 s = reinterpret_cast<const float4*>(sg[g])[f4];
                acc[g] += w.x * s.x + w.y * s.y + w.z * s.z + w.w * s.w;
            }
        }
#pragma unroll
        for (int g = 0; g < 32; g++)
            g_V[(size_t)(g0 + g) * Dc + d] = acc[g];
    } else {
        // tree_mask dtype sniffer (first 4096 words safe for all dtypes)
        __shared__ int ok_i32, ok_f32;
        if (threadIdx.x == 0) { ok_i32 = 1; ok_f32 = 1; }
        __syncthreads();
        int li = 1, lf = 1;
        for (int i = threadIdx.x; i < 4096; i += blockDim.x) {
            uint32_t w = mw[i];
            if (!(w == 0u || w == 1u)) li = 0;
            if (!(w == 0u || w == 0x3F800000u)) lf = 0;
        }
        if (!li) ok_i32 = 0;   // benign race: all writers store 0
        if (!lf) ok_f32 = 0;
        __syncthreads();
        if (threadIdx.x == 0) g_mask_kind = ok_i32 ? 1 : (ok_f32 ? 2 : 0);
    }
}

// ---------------------------------------------------------------------------
// Bucketing pass A: per-block privatized histogram (smem atomics only),
// written transposed: g_mat[t * NB + block].
// ---------------------------------------------------------------------------
__global__ void hist_local_kernel(const int* __restrict__ ei, int E, int CH) {
    __shared__ int h[NTGT];                 // 8 KB
    for (int i = threadIdx.x; i < NTGT; i += 256) h[i] = 0;
    __syncthreads();
    const int s = blockIdx.x * CH;
    const int e = (s + CH < E) ? s + CH : E;
    for (int i = s + threadIdx.x; i < e; i += 256)
        atomicAdd(&h[ei[E + i]], 1);
    __syncthreads();
    for (int i = threadIdx.x; i < NTGT; i += 256)
        g_mat[i * NB + blockIdx.x] = h[i];
}

// Pass B1: one WARP per tgt — int4 load (4 counts/lane), in-lane prefix +
// warp exclusive scan. Fully parallel (2048 warps).
__global__ void col_scan_kernel() {
    const int t = (blockIdx.x * blockDim.x + threadIdx.x) >> 5;
    const int lane = threadIdx.x & 31;
    if (t >= NTGT) return;
    int4 v = reinterpret_cast<const int4*>(g_mat + t * NB)[lane];
    const int s0 = v.x, s1 = s0 + v.y, s2 = s1 + v.z, s3 = s2 + v.w;
    int run = s3;
#pragma unroll
    for (int o = 1; o < 32; o <<= 1) {
        int u = __shfl_up_sync(0xffffffffu, run, o);
        if (lane >= o) run += u;
    }
    const int excl = run - s3;
    int4 w = make_int4(excl, excl + s0, excl + s1, excl + s2);
    reinterpret_cast<int4*>(g_mat + t * NB)[lane] = w;
    if (lane == 31) g_cnt[t] = run;
}

// Pass B2: single block, exclusive scan of g_cnt -> g_base.
__global__ void scan_kernel() {
    __shared__ int wsum[32];
    const int t = threadIdx.x, lane = t & 31, w = t >> 5;
    int a = g_cnt[2 * t], b = g_cnt[2 * t + 1];
    int s = a + b;
    int v = s;
#pragma unroll
    for (int o = 1; o < 32; o <<= 1) {
        int u = __shfl_up_sync(0xffffffffu, v, o);
        if (lane >= o) v += u;
    }
    if (lane == 31) wsum[w] = v;
    __syncthreads();
    if (w == 0) {
        int x = wsum[lane];
#pragma unroll
        for (int o = 1; o < 32; o <<= 1) {
            int u = __shfl_up_sync(0xffffffffu, x, o);
            if (lane >= o) x += u;
        }
        wsum[lane] = x;
    }
    __syncthreads();
    int excl = v - s + (w ? wsum[w - 1] : 0);
    g_base[2 * t] = excl;
    g_base[2 * t + 1] = excl + a;
}

// Pass C: scatter with per-block smem offsets (absolute bases preloaded).
__global__ void scatter2_kernel(const int* __restrict__ ei, int E, int CH) {
    __shared__ int off[NTGT];               // 8 KB
    for (int i = threadIdx.x; i < NTGT; i += 256)
        off[i] = g_base[i] + g_mat[i * NB + blockIdx.x];
    __syncthreads();
    const int s = blockIdx.x * CH;
    const int e = (s + CH < E) ? s + CH : E;
    for (int i = s + threadIdx.x; i < e; i += 256) {
        const int t = ei[E + i];
        const int p = atomicAdd(&off[t], 1);
        g_pair[p] = make_int2(i, ei[i]);
    }
}

// ---------------------------------------------------------------------------
// Kernel 2: lemma_preds[e] = dot(scope_fp16[src[e]], V_fp32[tgt]) + bias.
// One block per tgt bucket; lane owns 8 consecutive d's: V segment in regs,
// scope segment = ONE LDG.128 of halfs per edge. 4 edges per warp-iteration,
// interleaved shfl reduction chains.
// ---------------------------------------------------------------------------
__global__ void edge_grouped_kernel(const float* __restrict__ bias,
                                    float* __restrict__ out) {
    __shared__ float sV[Dc];
    const int tgt = blockIdx.x;
    for (int i = threadIdx.x; i < Dc; i += 256)
        sV[i] = g_V[(size_t)tgt * Dc + i];
    __syncthreads();

    const int w = threadIdx.x >> 5, lane = threadIdx.x & 31;
    const float4 va = *reinterpret_cast<const float4*>(sV + lane * 8);
    const float4 vb = *reinterpret_cast<const float4*>(sV + lane * 8 + 4);
    const float b0 = __ldg(bias);
    const int base = g_base[tgt], cnt = g_cnt[tgt];

    for (int i = 4 * w; i < cnt; i += 32) {
        const int nj = (cnt - i < 4) ? (cnt - i) : 4;
        float acc[4];
        int eid[4];
#pragma unroll
        for (int j = 0; j < 4; j++) {
            acc[j] = 0.f;
            if (j < nj) {
                const int2 p = g_pair[base + i + j];
                eid[j] = p.x;
                const uint4 hv = *reinterpret_cast<const uint4*>(
                    g_Sh + (size_t)p.y * Dc + lane * 8);
                const __half2 h0 = *reinterpret_cast<const __half2*>(&hv.x);
                const __half2 h1 = *reinterpret_cast<const __half2*>(&hv.y);
                const __half2 h2 = *reinterpret_cast<const __half2*>(&hv.z);
                const __half2 h3 = *reinterpret_cast<const __half2*>(&hv.w);
                const float2 f0 = __half22float2(h0);
                const float2 f1 = __half22float2(h1);
                const float2 f2 = __half22float2(h2);
                const float2 f3 = __half22float2(h3);
                acc[j] = f0.x * va.x + f0.y * va.y + f1.x * va.z + f1.y * va.w
                       + f2.x * vb.x + f2.y * vb.y + f3.x * vb.z + f3.y * vb.w;
            }
        }
#pragma unroll
        for (int o = 16; o; o >>= 1) {
            acc[0] += __shfl_xor_sync(0xffffffffu, acc[0], o);
            acc[1] += __shfl_xor_sync(0xffffffffu, acc[1], o);
            acc[2] += __shfl_xor_sync(0xffffffffu, acc[2], o);
            acc[3] += __shfl_xor_sync(0xffffffffu, acc[3], o);
        }
        if (lane == 0) {
#pragma unroll
            for (int j = 0; j < 4; j++)
                if (j < nj) out[eid[j]] = acc[j] + b0;
        }
    }
}

// ---------------------------------------------------------------------------
// Kernel 3: lm_preds — shared-memory micro-GEMM (fp32, unchanged).
// ---------------------------------------------------------------------------
#define NT 32
#define MG 4
__global__ void lm_kernel2(const float* __restrict__ scope,
                           const int* __restrict__ lm_idx,
                           const int* __restrict__ bpts,
                           const void* __restrict__ tree_mask,
                           float* __restrict__ out, int M) {
    __shared__ float sS[Dc * NT];          // 32 KB, [d][n^sw(d)]
    __shared__ float sM[Dc * MG];          // 4 KB, [d][mi]
    __shared__ float sP[8 * MG * NT];      // 4 KB, [q][mi][n]
    __shared__ int   s_list[1024];
    __shared__ int   s_cnt;
    __shared__ unsigned s_tm;

    const int b = blockIdx.y;
    const int n0 = blockIdx.x * NT;
    const int tid = threadIdx.x, lane = tid & 31, q = tid >> 5;

    if (tid == 0) s_cnt = 0;
    __syncthreads();

    for (int m = tid; m < M; m += 256)
        if (bpts[m] == b) {
            int p = atomicAdd(&s_cnt, 1);
            s_list[p] = m;
        }

    if (q == 0) {
        const int n = n0 + lane;
        const int kind = g_mask_kind;
        bool mk;
        if (kind == 0)      mk = ((const uint8_t*)tree_mask)[b * Nc + n] != 0;
        else if (kind == 1) mk = ((const int*)tree_mask)[b * Nc + n] != 0;
        else                mk = ((const float*)tree_mask)[b * Nc + n] != 0.f;
        unsigned bal = __ballot_sync(0xffffffffu, mk);
        if (lane == 0) s_tm = bal;
    }

    // stage scope tile transposed + swizzled: (d,n) at [d*NT + (n^((d>>2)&31))]
    for (int idx = tid; idx < NT * (Dc / 4); idx += 256) {
        const int n = idx >> 6, d4 = idx & 63;
        float4 v = *reinterpret_cast<const float4*>(
            scope + (size_t)(b * Nc + n0 + n) * (Tc * Dc) + d4 * 4);
        const int d = d4 * 4;
        const int sw = d4 & 31;
        sS[(d + 0) * NT + (n ^ sw)] = v.x;
        sS[(d + 1) * NT + (n ^ sw)] = v.y;
        sS[(d + 2) * NT + (n ^ sw)] = v.z;
        sS[(d + 3) * NT + (n ^ sw)] = v.w;
    }
    __syncthreads();

    const int cnt = (s_cnt < M) ? s_cnt : M;
    const unsigned tmbits = s_tm;

    for (int i0 = 0; i0 < cnt; i0 += MG) {
        const int g = (cnt - i0 < MG) ? (cnt - i0) : MG;
        for (int idx = tid; idx < g * Dc; idx += 256) {
            const int mi = idx >> 8, d = idx & 255;
            sM[d * MG + mi] = scope[(size_t)lm_idx[s_list[i0 + mi]] * Dc + d];
        }
        __syncthreads();

        float acc0 = 0.f, acc1 = 0.f, acc2 = 0.f, acc3 = 0.f;
#pragma unroll
        for (int i = 0; i < 32; i++) {
            const int d = q * 32 + i;
            const float sval = sS[d * NT + (lane ^ ((d >> 2) & 31))];
            const float4 mv = *reinterpret_cast<const float4*>(sM + d * MG);
            acc0 += sval * mv.x;
            acc1 += sval * mv.y;
            acc2 += sval * mv.z;
            acc3 += sval * mv.w;
        }
        sP[(q * MG + 0) * NT + lane] = acc0;
        sP[(q * MG + 1) * NT + lane] = acc1;
        sP[(q * MG + 2) * NT + lane] = acc2;
        sP[(q * MG + 3) * NT + lane] = acc3;
        __syncthreads();

        if (tid < 32 * g) {
            const int n = lane, mi = q;
            float sum = 0.f;
#pragma unroll
            for (int qq = 0; qq < 8; qq++)
                sum += sP[(qq * MG + mi) * NT + n];
            const int m = s_list[i0 + mi];
            out[(size_t)m * Nc + n0 + n] = ((tmbits >> n) & 1u) ? sum : NEGV;
        }
        __syncthreads();
    }
}

// ---------------------------------------------------------------------------
// Launcher. Inputs: scope, goal, W, bias, edge_index, lm_mask_idx, batch_pts,
// tree_mask. Output: [lemma_preds (E) | lm_preds (M*Nc)] float32.
// ---------------------------------------------------------------------------
extern "C" void kernel_launch(void* const* d_in, const int* in_sizes, int n_in,
                              void* d_out, int out_size) {
    const float* scope = (const float*)d_in[0];
    const float* goal  = (const float*)d_in[1];
    const float* W     = (const float*)d_in[2];
    const float* bias  = (const float*)d_in[3];
    const int*   ei    = (const int*)d_in[4];
    const int*   lmidx = (const int*)d_in[5];
    const int*   bpts  = (const int*)d_in[6];
    const void*  tmask = d_in[7];
    float* out = (float*)d_out;

    const int E = in_sizes[4] / 2;
    const int M = in_sizes[5];
    const int CH = (E + NB - 1) / NB;

    prep_kernel<<<193, 256>>>(scope, goal, W, (const uint32_t*)tmask);

    hist_local_kernel<<<NB, 256>>>(ei, E, CH);
    col_scan_kernel<<<NTGT * 32 / 256, 256>>>();
    scan_kernel<<<1, 1024>>>();
    scatter2_kernel<<<NB, 256>>>(ei, E, CH);

    edge_grouped_kernel<<<NTGT, 256>>>(bias, out);
    lm_kernel2<<<dim3(Nc / NT, Bc), 256>>>(scope, lmidx, bpts, tmask,
                                           out + E, M);
}

// round 10
// speedup vs baseline: 1.2000x; 1.2000x over previous
#include <cuda_runtime.h>
#include <cuda_fp16.h>
#include <stdint.h>

// Problem constants
#define Bc 32
#define Nc 512
#define Gc 64
#define Tc 16
#define Dc 256
#define NTGT (Bc * Gc)          // 2048 goal rows
#define NSRC (Bc * Nc)          // 16384 scope rows
#define EMAX 500000
#define NB 128                  // bucketing blocks

static __device__ __constant__ float NEGV = -1.0e10f;

// Scratch (static __device__ per harness rules)
__device__ float  g_V[NTGT * Dc];      // V[g][d] = W @ goal_type[g]   (2 MB)
__device__ __half g_Sh[NSRC * Dc];     // fp16 copy of scope_type rows (8 MB)
__device__ int    g_cnt[NTGT];
__device__ int    g_base[NTGT];
__device__ int    g_mat[NTGT * NB];    // transposed [tgt][block] counts->prefixes
__device__ int2   g_pair[EMAX];        // (edge id, src) grouped by tgt (4 MB)
__device__ int    g_mask_kind;         // 0=u8, 1=i32, 2=f32
__device__ int    g_done;              // last-block ticket (reset each launch)

// ---------------------------------------------------------------------------
// Kernel 1 (launch #1): mega-prep.
//   blocks [0,128):   fp16 conversion of scope_type rows
//   blocks [128,192): V = W @ goal_type (32 g's per block)
//   block  192:       tree_mask dtype sniffer
//   blocks [193,321): privatized histogram of tgt (transposed g_mat)
// All parts independent; 321 blocks fit in one wave (32KB smem -> 7/SM).
// ---------------------------------------------------------------------------
__global__ void prep_kernel(const float* __restrict__ scope,
                            const float* __restrict__ goal,
                            const float* __restrict__ W,
                            const uint32_t* __restrict__ mw,
                            const int* __restrict__ ei, int E, int CH) {
    __shared__ int sbuf[8192];             // 32 KB, aliased per role
    const int blk = blockIdx.x;
    if (blk < 128) {
        // fp16 conversion: 128 rows per block, warp per row, 16 rows per warp
        const int w = threadIdx.x >> 5, lane = threadIdx.x & 31;
#pragma unroll 4
        for (int r = 0; r < 16; r++) {
            const int row = blk * 128 + w * 16 + r;
            const float4* src =
                reinterpret_cast<const float4*>(scope + (size_t)row * (Tc * Dc));
            float4 x = src[lane * 2], y = src[lane * 2 + 1];
            __half2 h0 = __floats2half2_rn(x.x, x.y);
            __half2 h1 = __floats2half2_rn(x.z, x.w);
            __half2 h2 = __floats2half2_rn(y.x, y.y);
            __half2 h3 = __floats2half2_rn(y.z, y.w);
            uint4 packed;
            packed.x = *reinterpret_cast<uint32_t*>(&h0);
            packed.y = *reinterpret_cast<uint32_t*>(&h1);
            packed.z = *reinterpret_cast<uint32_t*>(&h2);
            packed.w = *reinterpret_cast<uint32_t*>(&h3);
            reinterpret_cast<uint4*>(g_Sh + (size_t)row * Dc)[lane] = packed;
        }
    } else if (blk < 192) {
        // V[g][d] = sum_f W[d][f] * goal_type[g][f]
        float (*sg)[Dc] = reinterpret_cast<float (*)[Dc]>(sbuf);
        const int g0 = (blk - 128) * 32;
        for (int i = threadIdx.x; i < 32 * Dc; i += blockDim.x) {
            int g = i >> 8, f = i & 255;
            sg[g][f] = goal[(size_t)(g0 + g) * (Tc * Dc) + f];
        }
        __syncthreads();
        const int d = threadIdx.x;
        float acc[32];
#pragma unroll
        for (int g = 0; g < 32; g++) acc[g] = 0.f;
        const float4* Wrow = reinterpret_cast<const float4*>(W + (size_t)d * Dc);
#pragma unroll 4
        for (int f4 = 0; f4 < Dc / 4; f4++) {
            float4 w = Wrow[f4];
#pragma unroll
            for (int g = 0; g < 32; g++) {
                float4 s = reinterpret_cast<const float4*>(sg[g])[f4];
                acc[g] += w.x * s.x + w.y * s.y + w.z * s.z + w.w * s.w;
            }
        }
#pragma unroll
        for (int g = 0; g < 32; g++)
            g_V[(size_t)(g0 + g) * Dc + d] = acc[g];
    } else if (blk == 192) {
        // mask dtype sniffer (first 4096 words safe for all candidate dtypes)
        if (threadIdx.x == 0) { sbuf[0] = 1; sbuf[1] = 1; }
        __syncthreads();
        int li = 1, lf = 1;
        for (int i = threadIdx.x; i < 4096; i += blockDim.x) {
            uint32_t w = mw[i];
            if (!(w == 0u || w == 1u)) li = 0;
            if (!(w == 0u || w == 0x3F800000u)) lf = 0;
        }
        if (!li) sbuf[0] = 0;   // benign race: all writers store 0
        if (!lf) sbuf[1] = 0;
        __syncthreads();
        if (threadIdx.x == 0) g_mask_kind = sbuf[0] ? 1 : (sbuf[1] ? 2 : 0);
    } else {
        // privatized histogram, transposed store: g_mat[t*NB + hb]
        const int hb = blk - 193;
        int* h = sbuf;                      // 8 KB used
        for (int i = threadIdx.x; i < NTGT; i += 256) h[i] = 0;
        __syncthreads();
        const int s = hb * CH;
        const int e = (s + CH < E) ? s + CH : E;
        for (int i = s + threadIdx.x; i < e; i += 256)
            atomicAdd(&h[ei[E + i]], 1);
        __syncthreads();
        for (int i = threadIdx.x; i < NTGT; i += 256)
            g_mat[i * NB + hb] = h[i];
    }
}

// ---------------------------------------------------------------------------
// Kernel 2 (launch #2): per-tgt warp scan of g_mat rows + g_cnt totals,
// then the LAST block (ticket) does the 2048-wide exclusive scan -> g_base
// and resets the ticket for graph replay.
// ---------------------------------------------------------------------------
__global__ void colscan_scan_kernel() {
    __shared__ int wsum[8];
    const int t = (blockIdx.x * blockDim.x + threadIdx.x) >> 5;
    const int lane = threadIdx.x & 31;

    int4 v = reinterpret_cast<const int4*>(g_mat + t * NB)[lane];
    const int s0 = v.x, s1 = s0 + v.y, s2 = s1 + v.z, s3 = s2 + v.w;
    int run = s3;
#pragma unroll
    for (int o = 1; o < 32; o <<= 1) {
        int u = __shfl_up_sync(0xffffffffu, run, o);
        if (lane >= o) run += u;
    }
    const int excl = run - s3;
    int4 w = make_int4(excl, excl + s0, excl + s1, excl + s2);
    reinterpret_cast<int4*>(g_mat + t * NB)[lane] = w;
    if (lane == 31) g_cnt[t] = run;

    // last-block ticket
    __shared__ int is_last;
    __threadfence();
    __syncthreads();
    if (threadIdx.x == 0) {
        int ticket = atomicAdd(&g_done, 1);
        is_last = (ticket == (int)gridDim.x - 1);
    }
    __syncthreads();
    if (!is_last) return;

    // exclusive scan of g_cnt[0..2047] with this block's 256 threads
    const int tid = threadIdx.x, ln = tid & 31, wp = tid >> 5;
    int c[8], run2 = 0;
#pragma unroll
    for (int k = 0; k < 8; k++) { c[k] = g_cnt[tid * 8 + k]; run2 += c[k]; }
    int v2 = run2;
#pragma unroll
    for (int o = 1; o < 32; o <<= 1) {
        int u = __shfl_up_sync(0xffffffffu, v2, o);
        if (ln >= o) v2 += u;
    }
    if (ln == 31) wsum[wp] = v2;
    __syncthreads();
    if (wp == 0 && ln < 8) {
        int x = wsum[ln];
#pragma unroll
        for (int o = 1; o < 8; o <<= 1) {
            int u = __shfl_up_sync(0xffu, x, o);
            if (ln >= o) x += u;
        }
        wsum[ln] = x;
    }
    __syncthreads();
    int base = v2 - run2 + (wp ? wsum[wp - 1] : 0);
#pragma unroll
    for (int k = 0; k < 8; k++) { g_base[tid * 8 + k] = base; base += c[k]; }
    if (tid == 0) g_done = 0;    // reset for next graph replay
}

// ---------------------------------------------------------------------------
// Kernel 3 (launch #3): scatter with per-block smem offsets.
// ---------------------------------------------------------------------------
__global__ void scatter2_kernel(const int* __restrict__ ei, int E, int CH) {
    __shared__ int off[NTGT];               // 8 KB
    for (int i = threadIdx.x; i < NTGT; i += 256)
        off[i] = g_base[i] + g_mat[i * NB + blockIdx.x];
    __syncthreads();
    const int s = blockIdx.x * CH;
    const int e = (s + CH < E) ? s + CH : E;
    for (int i = s + threadIdx.x; i < e; i += 256) {
        const int t = ei[E + i];
        const int p = atomicAdd(&off[t], 1);
        g_pair[p] = make_int2(i, ei[i]);
    }
}

// ---------------------------------------------------------------------------
// Kernel 4 (launch #4 — ncu capture slot): edge dot products.
// lemma_preds[e] = dot(scope_fp16[src[e]], V_fp32[tgt]) + bias.
// One block per tgt; lane owns 8 d's (V in regs, one LDG.128 of halfs per
// edge). 4 edges per warp-iteration, interleaved shfl reductions.
// ---------------------------------------------------------------------------
__global__ void edge_grouped_kernel(const float* __restrict__ bias,
                                    float* __restrict__ out) {
    __shared__ float sV[Dc];
    const int tgt = blockIdx.x;
    for (int i = threadIdx.x; i < Dc; i += 256)
        sV[i] = g_V[(size_t)tgt * Dc + i];
    __syncthreads();

    const int w = threadIdx.x >> 5, lane = threadIdx.x & 31;
    const float4 va = *reinterpret_cast<const float4*>(sV + lane * 8);
    const float4 vb = *reinterpret_cast<const float4*>(sV + lane * 8 + 4);
    const float b0 = __ldg(bias);
    const int base = g_base[tgt], cnt = g_cnt[tgt];

    for (int i = 4 * w; i < cnt; i += 32) {
        const int nj = (cnt - i < 4) ? (cnt - i) : 4;
        float acc[4];
        int eid[4];
#pragma unroll
        for (int j = 0; j < 4; j++) {
            acc[j] = 0.f;
            if (j < nj) {
                const int2 p = g_pair[base + i + j];
                eid[j] = p.x;
                const uint4 hv = *reinterpret_cast<const uint4*>(
                    g_Sh + (size_t)p.y * Dc + lane * 8);
                const __half2 h0 = *reinterpret_cast<const __half2*>(&hv.x);
                const __half2 h1 = *reinterpret_cast<const __half2*>(&hv.y);
                const __half2 h2 = *reinterpret_cast<const __half2*>(&hv.z);
                const __half2 h3 = *reinterpret_cast<const __half2*>(&hv.w);
                const float2 f0 = __half22float2(h0);
                const float2 f1 = __half22float2(h1);
                const float2 f2 = __half22float2(h2);
                const float2 f3 = __half22float2(h3);
                acc[j] = f0.x * va.x + f0.y * va.y + f1.x * va.z + f1.y * va.w
                       + f2.x * vb.x + f2.y * vb.y + f3.x * vb.z + f3.y * vb.w;
            }
        }
#pragma unroll
        for (int o = 16; o; o >>= 1) {
            acc[0] += __shfl_xor_sync(0xffffffffu, acc[0], o);
            acc[1] += __shfl_xor_sync(0xffffffffu, acc[1], o);
            acc[2] += __shfl_xor_sync(0xffffffffu, acc[2], o);
            acc[3] += __shfl_xor_sync(0xffffffffu, acc[3], o);
        }
        if (lane == 0) {
#pragma unroll
            for (int j = 0; j < 4; j++)
                if (j < nj) out[eid[j]] = acc[j] + b0;
        }
    }
}

// ---------------------------------------------------------------------------
// Kernel 5 (launch #5): lm_preds shared-memory micro-GEMM (fp32).
// ---------------------------------------------------------------------------
#define NT 32
#define MG 4
__global__ void lm_kernel2(const float* __restrict__ scope,
                           const int* __restrict__ lm_idx,
                           const int* __restrict__ bpts,
                           const void* __restrict__ tree_mask,
                           float* __restrict__ out, int M) {
    __shared__ float sS[Dc * NT];          // 32 KB, [d][n^sw(d)]
    __shared__ float sM[Dc * MG];          // 4 KB, [d][mi]
    __shared__ float sP[8 * MG * NT];      // 4 KB, [q][mi][n]
    __shared__ int   s_list[1024];
    __shared__ int   s_cnt;
    __shared__ unsigned s_tm;

    const int b = blockIdx.y;
    const int n0 = blockIdx.x * NT;
    const int tid = threadIdx.x, lane = tid & 31, q = tid >> 5;

    if (tid == 0) s_cnt = 0;
    __syncthreads();

    for (int m = tid; m < M; m += 256)
        if (bpts[m] == b) {
            int p = atomicAdd(&s_cnt, 1);
            s_list[p] = m;
        }

    if (q == 0) {
        const int n = n0 + lane;
        const int kind = g_mask_kind;
        bool mk;
        if (kind == 0)      mk = ((const uint8_t*)tree_mask)[b * Nc + n] != 0;
        else if (kind == 1) mk = ((const int*)tree_mask)[b * Nc + n] != 0;
        else                mk = ((const float*)tree_mask)[b * Nc + n] != 0.f;
        unsigned bal = __ballot_sync(0xffffffffu, mk);
        if (lane == 0) s_tm = bal;
    }

    for (int idx = tid; idx < NT * (Dc / 4); idx += 256) {
        const int n = idx >> 6, d4 = idx & 63;
        float4 v = *reinterpret_cast<const float4*>(
            scope + (size_t)(b * Nc + n0 + n) * (Tc * Dc) + d4 * 4);
        const int d = d4 * 4;
        const int sw = d4 & 31;
        sS[(d + 0) * NT + (n ^ sw)] = v.x;
        sS[(d + 1) * NT + (n ^ sw)] = v.y;
        sS[(d + 2) * NT + (n ^ sw)] = v.z;
        sS[(d + 3) * NT + (n ^ sw)] = v.w;
    }
    __syncthreads();

    const int cnt = (s_cnt < M) ? s_cnt : M;
    const unsigned tmbits = s_tm;

    for (int i0 = 0; i0 < cnt; i0 += MG) {
        const int g = (cnt - i0 < MG) ? (cnt - i0) : MG;
        for (int idx = tid; idx < g * Dc; idx += 256) {
            const int mi = idx >> 8, d = idx & 255;
            sM[d * MG + mi] = scope[(size_t)lm_idx[s_list[i0 + mi]] * Dc + d];
        }
        __syncthreads();

        float acc0 = 0.f, acc1 = 0.f, acc2 = 0.f, acc3 = 0.f;
#pragma unroll
        for (int i = 0; i < 32; i++) {
            const int d = q * 32 + i;
            const float sval = sS[d * NT + (lane ^ ((d >> 2) & 31))];
            const float4 mv = *reinterpret_cast<const float4*>(sM + d * MG);
            acc0 += sval * mv.x;
            acc1 += sval * mv.y;
            acc2 += sval * mv.z;
            acc3 += sval * mv.w;
        }
        sP[(q * MG + 0) * NT + lane] = acc0;
        sP[(q * MG + 1) * NT + lane] = acc1;
        sP[(q * MG + 2) * NT + lane] = acc2;
        sP[(q * MG + 3) * NT + lane] = acc3;
        __syncthreads();

        if (tid < 32 * g) {
            const int n = lane, mi = q;
            float sum = 0.f;
#pragma unroll
            for (int qq = 0; qq < 8; qq++)
                sum += sP[(qq * MG + mi) * NT + n];
            const int m = s_list[i0 + mi];
            out[(size_t)m * Nc + n0 + n] = ((tmbits >> n) & 1u) ? sum : NEGV;
        }
        __syncthreads();
    }
}

// ---------------------------------------------------------------------------
// Launcher. Inputs: scope, goal, W, bias, edge_index, lm_mask_idx, batch_pts,
// tree_mask. Output: [lemma_preds (E) | lm_preds (M*Nc)] float32.
// ---------------------------------------------------------------------------
extern "C" void kernel_launch(void* const* d_in, const int* in_sizes, int n_in,
                              void* d_out, int out_size) {
    const float* scope = (const float*)d_in[0];
    const float* goal  = (const float*)d_in[1];
    const float* W     = (const float*)d_in[2];
    const float* bias  = (const float*)d_in[3];
    const int*   ei    = (const int*)d_in[4];
    const int*   lmidx = (const int*)d_in[5];
    const int*   bpts  = (const int*)d_in[6];
    const void*  tmask = d_in[7];
    float* out = (float*)d_out;

    const int E = in_sizes[4] / 2;
    const int M = in_sizes[5];
    const int CH = (E + NB - 1) / NB;

    prep_kernel<<<193 + NB, 256>>>(scope, goal, W, (const uint32_t*)tmask,
                                   ei, E, CH);
    colscan_scan_kernel<<<NTGT * 32 / 256, 256>>>();
    scatter2_kernel<<<NB, 256>>>(ei, E, CH);
    edge_grouped_kernel<<<NTGT, 256>>>(bias, out);
    lm_kernel2<<<dim3(Nc / NT, Bc), 256>>>(scope, lmidx, bpts, tmask,
                                           out + E, M);
}

// round 12
// speedup vs baseline: 1.4809x; 1.2340x over previous
#include <cuda_runtime.h>
#include <cuda_fp16.h>
#include <stdint.h>

// Problem constants
#define Bc 32
#define Nc 512
#define Gc 64
#define Tc 16
#define Dc 256
#define NTGT (Bc * Gc)          // 2048 goal rows
#define NSRC (Bc * Nc)          // 16384 scope rows
#define EMAX 500000
#define NB 128                  // bucketing blocks

static __device__ __constant__ float NEGV = -1.0e10f;

// Scratch (static __device__ per harness rules)
__device__ float  g_V[NTGT * Dc];      // V[g][d] = W @ goal_type[g]   (2 MB)
__device__ __half g_Sh[NSRC * Dc];     // fp16 copy of scope_type rows (8 MB)
__device__ int    g_cnt[NTGT];
__device__ int    g_base[NTGT];
__device__ int    g_mat[NTGT * NB];    // transposed [tgt][block] counts->prefixes
__device__ int2   g_pair[EMAX];        // (edge id, src) grouped by tgt (4 MB)
__device__ int    g_mask_kind;         // 0=u8, 1=i32, 2=f32
__device__ int    g_done;              // last-block ticket (reset each launch)

// ---------------------------------------------------------------------------
// prepA (stream 0): fp16 conversion [0,128) + V GEMM [128,192) + sniffer 192.
// ---------------------------------------------------------------------------
__global__ void prepA_kernel(const float* __restrict__ scope,
                             const float* __restrict__ goal,
                             const float* __restrict__ W,
                             const uint32_t* __restrict__ mw) {
    __shared__ int sbuf[8192];             // 32 KB, aliased per role
    const int blk = blockIdx.x;
    if (blk < 128) {
        const int w = threadIdx.x >> 5, lane = threadIdx.x & 31;
#pragma unroll 4
        for (int r = 0; r < 16; r++) {
            const int row = blk * 128 + w * 16 + r;
            const float4* src =
                reinterpret_cast<const float4*>(scope + (size_t)row * (Tc * Dc));
            float4 x = src[lane * 2], y = src[lane * 2 + 1];
            __half2 h0 = __floats2half2_rn(x.x, x.y);
            __half2 h1 = __floats2half2_rn(x.z, x.w);
            __half2 h2 = __floats2half2_rn(y.x, y.y);
            __half2 h3 = __floats2half2_rn(y.z, y.w);
            uint4 packed;
            packed.x = *reinterpret_cast<uint32_t*>(&h0);
            packed.y = *reinterpret_cast<uint32_t*>(&h1);
            packed.z = *reinterpret_cast<uint32_t*>(&h2);
            packed.w = *reinterpret_cast<uint32_t*>(&h3);
            reinterpret_cast<uint4*>(g_Sh + (size_t)row * Dc)[lane] = packed;
        }
    } else if (blk < 192) {
        float (*sg)[Dc] = reinterpret_cast<float (*)[Dc]>(sbuf);
        const int g0 = (blk - 128) * 32;
        for (int i = threadIdx.x; i < 32 * Dc; i += blockDim.x) {
            int g = i >> 8, f = i & 255;
            sg[g][f] = goal[(size_t)(g0 + g) * (Tc * Dc) + f];
        }
        __syncthreads();
        const int d = threadIdx.x;
        float acc[32];
#pragma unroll
        for (int g = 0; g < 32; g++) acc[g] = 0.f;
        const float4* Wrow = reinterpret_cast<const float4*>(W + (size_t)d * Dc);
#pragma unroll 4
        for (int f4 = 0; f4 < Dc / 4; f4++) {
            float4 w = Wrow[f4];
#pragma unroll
            for (int g = 0; g < 32; g++) {
                float4 s = reinterpret_cast<const float4*>(sg[g])[f4];
                acc[g] += w.x * s.x + w.y * s.y + w.z * s.z + w.w * s.w;
            }
        }
#pragma unroll
        for (int g = 0; g < 32; g++)
            g_V[(size_t)(g0 + g) * Dc + d] = acc[g];
    } else {
        // mask dtype sniffer (first 4096 words safe for all candidate dtypes)
        if (threadIdx.x == 0) { sbuf[0] = 1; sbuf[1] = 1; }
        __syncthreads();
        int li = 1, lf = 1;
        for (int i = threadIdx.x; i < 4096; i += blockDim.x) {
            uint32_t w = mw[i];
            if (!(w == 0u || w == 1u)) li = 0;
            if (!(w == 0u || w == 0x3F800000u)) lf = 0;
        }
        if (!li) sbuf[0] = 0;   // benign race: all writers store 0
        if (!lf) sbuf[1] = 0;
        __syncthreads();
        if (threadIdx.x == 0) g_mask_kind = sbuf[0] ? 1 : (sbuf[1] ? 2 : 0);
    }
}

// ---------------------------------------------------------------------------
// chain B kernel 1 (s1): privatized histogram, transposed store.
// ---------------------------------------------------------------------------
__global__ void hist_kernel(const int* __restrict__ ei, int E, int CH) {
    __shared__ int h[NTGT];                 // 8 KB
    for (int i = threadIdx.x; i < NTGT; i += 256) h[i] = 0;
    __syncthreads();
    const int s = blockIdx.x * CH;
    const int e = (s + CH < E) ? s + CH : E;
    for (int i = s + threadIdx.x; i < e; i += 256)
        atomicAdd(&h[ei[E + i]], 1);
    __syncthreads();
    for (int i = threadIdx.x; i < NTGT; i += 256)
        g_mat[i * NB + blockIdx.x] = h[i];
}

// ---------------------------------------------------------------------------
// chain B kernel 2 (s1): per-tgt warp scan, then last-block ticket does the
// 2048-wide exclusive scan -> g_base and resets the ticket for graph replay.
// ---------------------------------------------------------------------------
__global__ void colscan_scan_kernel() {
    __shared__ int wsum[8];
    const int t = (blockIdx.x * blockDim.x + threadIdx.x) >> 5;
    const int lane = threadIdx.x & 31;

    int4 v = reinterpret_cast<const int4*>(g_mat + t * NB)[lane];
    const int s0 = v.x, s1 = s0 + v.y, s2 = s1 + v.z, s3 = s2 + v.w;
    int run = s3;
#pragma unroll
    for (int o = 1; o < 32; o <<= 1) {
        int u = __shfl_up_sync(0xffffffffu, run, o);
        if (lane >= o) run += u;
    }
    const int excl = run - s3;
    int4 w = make_int4(excl, excl + s0, excl + s1, excl + s2);
    reinterpret_cast<int4*>(g_mat + t * NB)[lane] = w;
    if (lane == 31) g_cnt[t] = run;

    __shared__ int is_last;
    __threadfence();
    __syncthreads();
    if (threadIdx.x == 0) {
        int ticket = atomicAdd(&g_done, 1);
        is_last = (ticket == (int)gridDim.x - 1);
    }
    __syncthreads();
    if (!is_last) return;

    const int tid = threadIdx.x, ln = tid & 31, wp = tid >> 5;
    int c[8], run2 = 0;
#pragma unroll
    for (int k = 0; k < 8; k++) { c[k] = g_cnt[tid * 8 + k]; run2 += c[k]; }
    int v2 = run2;
#pragma unroll
    for (int o = 1; o < 32; o <<= 1) {
        int u = __shfl_up_sync(0xffffffffu, v2, o);
        if (ln >= o) v2 += u;
    }
    if (ln == 31) wsum[wp] = v2;
    __syncthreads();
    if (wp == 0 && ln < 8) {
        int x = wsum[ln];
#pragma unroll
        for (int o = 1; o < 8; o <<= 1) {
            int u = __shfl_up_sync(0xffu, x, o);
            if (ln >= o) x += u;
        }
        wsum[ln] = x;
    }
    __syncthreads();
    int base = v2 - run2 + (wp ? wsum[wp - 1] : 0);
#pragma unroll
    for (int k = 0; k < 8; k++) { g_base[tid * 8 + k] = base; base += c[k]; }
    if (tid == 0) g_done = 0;    // reset for next graph replay
}

// ---------------------------------------------------------------------------
// chain B kernel 3 (s1): scatter with per-block smem offsets.
// ---------------------------------------------------------------------------
__global__ void scatter2_kernel(const int* __restrict__ ei, int E, int CH) {
    __shared__ int off[NTGT];               // 8 KB
    for (int i = threadIdx.x; i < NTGT; i += 256)
        off[i] = g_base[i] + g_mat[i * NB + blockIdx.x];
    __syncthreads();
    const int s = blockIdx.x * CH;
    const int e = (s + CH < E) ? s + CH : E;
    for (int i = s + threadIdx.x; i < e; i += 256) {
        const int t = ei[E + i];
        const int p = atomicAdd(&off[t], 1);
        g_pair[p] = make_int2(i, ei[i]);
    }
}

// ---------------------------------------------------------------------------
// edge (stream 0, after prepA + chain B): grouped fp16 dot products.
// ---------------------------------------------------------------------------
__global__ void edge_grouped_kernel(const float* __restrict__ bias,
                                    float* __restrict__ out) {
    __shared__ float sV[Dc];
    const int tgt = blockIdx.x;
    for (int i = threadIdx.x; i < Dc; i += 256)
        sV[i] = g_V[(size_t)tgt * Dc + i];
    __syncthreads();

    const int w = threadIdx.x >> 5, lane = threadIdx.x & 31;
    const float4 va = *reinterpret_cast<const float4*>(sV + lane * 8);
    const float4 vb = *reinterpret_cast<const float4*>(sV + lane * 8 + 4);
    const float b0 = __ldg(bias);
    const int base = g_base[tgt], cnt = g_cnt[tgt];

    for (int i = 4 * w; i < cnt; i += 32) {
        const int nj = (cnt - i < 4) ? (cnt - i) : 4;
        float acc[4];
        int eid[4];
#pragma unroll
        for (int j = 0; j < 4; j++) {
            acc[j] = 0.f;
            if (j < nj) {
                const int2 p = g_pair[base + i + j];
                eid[j] = p.x;
                const uint4 hv = *reinterpret_cast<const uint4*>(
                    g_Sh + (size_t)p.y * Dc + lane * 8);
                const __half2 h0 = *reinterpret_cast<const __half2*>(&hv.x);
                const __half2 h1 = *reinterpret_cast<const __half2*>(&hv.y);
                const __half2 h2 = *reinterpret_cast<const __half2*>(&hv.z);
                const __half2 h3 = *reinterpret_cast<const __half2*>(&hv.w);
                const float2 f0 = __half22float2(h0);
                const float2 f1 = __half22float2(h1);
                const float2 f2 = __half22float2(h2);
                const float2 f3 = __half22float2(h3);
                acc[j] = f0.x * va.x + f0.y * va.y + f1.x * va.z + f1.y * va.w
                       + f2.x * vb.x + f2.y * vb.y + f3.x * vb.z + f3.y * vb.w;
            }
        }
#pragma unroll
        for (int o = 16; o; o >>= 1) {
            acc[0] += __shfl_xor_sync(0xffffffffu, acc[0], o);
            acc[1] += __shfl_xor_sync(0xffffffffu, acc[1], o);
            acc[2] += __shfl_xor_sync(0xffffffffu, acc[2], o);
            acc[3] += __shfl_xor_sync(0xffffffffu, acc[3], o);
        }
        if (lane == 0) {
#pragma unroll
            for (int j = 0; j < 4; j++)
                if (j < nj) out[eid[j]] = acc[j] + b0;
        }
    }
}

// ---------------------------------------------------------------------------
// lm (s2, after prepA): shared-memory micro-GEMM (fp32).
// ---------------------------------------------------------------------------
#define NT 32
#define MG 4
__global__ void lm_kernel2(const float* __restrict__ scope,
                           const int* __restrict__ lm_idx,
                           const int* __restrict__ bpts,
                           const void* __restrict__ tree_mask,
                           float* __restrict__ out, int M) {
    __shared__ float sS[Dc * NT];          // 32 KB, [d][n^sw(d)]
    __shared__ float sM[Dc * MG];          // 4 KB, [d][mi]
    __shared__ float sP[8 * MG * NT];      // 4 KB, [q][mi][n]
    __shared__ int   s_list[1024];
    __shared__ int   s_cnt;
    __shared__ unsigned s_tm;

    const int b = blockIdx.y;
    const int n0 = blockIdx.x * NT;
    const int tid = threadIdx.x, lane = tid & 31, q = tid >> 5;

    if (tid == 0) s_cnt = 0;
    __syncthreads();

    for (int m = tid; m < M; m += 256)
        if (bpts[m] == b) {
            int p = atomicAdd(&s_cnt, 1);
            s_list[p] = m;
        }

    if (q == 0) {
        const int n = n0 + lane;
        const int kind = g_mask_kind;
        bool mk;
        if (kind == 0)      mk = ((const uint8_t*)tree_mask)[b * Nc + n] != 0;
        else if (kind == 1) mk = ((const int*)tree_mask)[b * Nc + n] != 0;
        else                mk = ((const float*)tree_mask)[b * Nc + n] != 0.f;
        unsigned bal = __ballot_sync(0xffffffffu, mk);
        if (lane == 0) s_tm = bal;
    }

    for (int idx = tid; idx < NT * (Dc / 4); idx += 256) {
        const int n = idx >> 6, d4 = idx & 63;
        float4 v = *reinterpret_cast<const float4*>(
            scope + (size_t)(b * Nc + n0 + n) * (Tc * Dc) + d4 * 4);
        const int d = d4 * 4;
        const int sw = d4 & 31;
        sS[(d + 0) * NT + (n ^ sw)] = v.x;
        sS[(d + 1) * NT + (n ^ sw)] = v.y;
        sS[(d + 2) * NT + (n ^ sw)] = v.z;
        sS[(d + 3) * NT + (n ^ sw)] = v.w;
    }
    __syncthreads();

    const int cnt = (s_cnt < M) ? s_cnt : M;
    const unsigned tmbits = s_tm;

    for (int i0 = 0; i0 < cnt; i0 += MG) {
        const int g = (cnt - i0 < MG) ? (cnt - i0) : MG;
        for (int idx = tid; idx < g * Dc; idx += 256) {
            const int mi = idx >> 8, d = idx & 255;
            sM[d * MG + mi] = scope[(size_t)lm_idx[s_list[i0 + mi]] * Dc + d];
        }
        __syncthreads();

        float acc0 = 0.f, acc1 = 0.f, acc2 = 0.f, acc3 = 0.f;
#pragma unroll
        for (int i = 0; i < 32; i++) {
            const int d = q * 32 + i;
            const float sval = sS[d * NT + (lane ^ ((d >> 2) & 31))];
            const float4 mv = *reinterpret_cast<const float4*>(sM + d * MG);
            acc0 += sval * mv.x;
            acc1 += sval * mv.y;
            acc2 += sval * mv.z;
            acc3 += sval * mv.w;
        }
        sP[(q * MG + 0) * NT + lane] = acc0;
        sP[(q * MG + 1) * NT + lane] = acc1;
        sP[(q * MG + 2) * NT + lane] = acc2;
        sP[(q * MG + 3) * NT + lane] = acc3;
        __syncthreads();

        if (tid < 32 * g) {
            const int n = lane, mi = q;
            float sum = 0.f;
#pragma unroll
            for (int qq = 0; qq < 8; qq++)
                sum += sP[(qq * MG + mi) * NT + n];
            const int m = s_list[i0 + mi];
            out[(size_t)m * Nc + n0 + n] = ((tmbits >> n) & 1u) ? sum : NEGV;
        }
        __syncthreads();
    }
}

// ---------------------------------------------------------------------------
// Launcher with stream fork/join (capturable). One-time stream/event setup
// happens on the first (uncaptured correctness) call; the captured graph is
// identical on every call.
// ---------------------------------------------------------------------------
struct AuxStreams {
    cudaStream_t s1, s2;
    cudaEvent_t  e0, eA, eB, eC;
    AuxStreams() {
        cudaStreamCreateWithFlags(&s1, cudaStreamNonBlocking);
        cudaStreamCreateWithFlags(&s2, cudaStreamNonBlocking);
        cudaEventCreateWithFlags(&e0, cudaEventDisableTiming);
        cudaEventCreateWithFlags(&eA, cudaEventDisableTiming);
        cudaEventCreateWithFlags(&eB, cudaEventDisableTiming);
        cudaEventCreateWithFlags(&eC, cudaEventDisableTiming);
    }
};

extern "C" void kernel_launch(void* const* d_in, const int* in_sizes, int n_in,
                              void* d_out, int out_size) {
    static AuxStreams aux;   // created once, before any graph capture

    const float* scope = (const float*)d_in[0];
    const float* goal  = (const float*)d_in[1];
    const float* W     = (const float*)d_in[2];
    const float* bias  = (const float*)d_in[3];
    const int*   ei    = (const int*)d_in[4];
    const int*   lmidx = (const int*)d_in[5];
    const int*   bpts  = (const int*)d_in[6];
    const void*  tmask = d_in[7];
    float* out = (float*)d_out;

    const int E = in_sizes[4] / 2;
    const int M = in_sizes[5];
    const int CH = (E + NB - 1) / NB;

    // Fork chain B (bucketing) onto s1 — independent of prepA.
    cudaEventRecord(aux.e0, 0);
    cudaStreamWaitEvent(aux.s1, aux.e0, 0);
    hist_kernel<<<NB, 256, 0, aux.s1>>>(ei, E, CH);
    colscan_scan_kernel<<<NTGT * 32 / 256, 256, 0, aux.s1>>>();
    scatter2_kernel<<<NB, 256, 0, aux.s1>>>(ei, E, CH);
    cudaEventRecord(aux.eB, aux.s1);

    // Chain A on stream 0: prepA (conv + V + sniffer), concurrent with B.
    prepA_kernel<<<193, 256>>>(scope, goal, W, (const uint32_t*)tmask);
    cudaEventRecord(aux.eA, 0);

    // Chain C: lm on s2, depends only on prepA (mask kind); overlaps edge.
    cudaStreamWaitEvent(aux.s2, aux.eA, 0);
    lm_kernel2<<<dim3(Nc / NT, Bc), 256, 0, aux.s2>>>(scope, lmidx, bpts,
                                                      tmask, out + E, M);
    cudaEventRecord(aux.eC, aux.s2);

    // Join B into stream 0, run edge, then join C.
    cudaStreamWaitEvent(0, aux.eB, 0);
    edge_grouped_kernel<<<NTGT, 256>>>(bias, out);
    cudaStreamWaitEvent(0, aux.eC, 0);
}